// round 1
// baseline (speedup 1.0000x reference)
#include <cuda_runtime.h>
#include <math.h>

#define ALPHA 0.2f
constexpr int Bc = 8;
constexpr int Nc = 2048;
constexpr int Cc = 128;
constexpr int NCHUNK = 16;           // 2048 / 128
constexpr int CHUNK = 128;

// ---------------- device scratch (no allocations allowed) ----------------
__device__ float g_h[Bc * Nc * Cc];          // h = text @ W
__device__ float g_s1[Bc * Nc];
__device__ float g_s2[Bc * Nc];
__device__ float g_v[Bc * Nc];               // sorted s2 (ascending) per batch
__device__ int   g_perm[Bc * Nc];            // permutation: sorted k -> original row j
__device__ float g_Ae[Bc * Nc];              // exp(alpha * v_k)
__device__ float g_Ee[Bc * Nc];              // exp(v_k - vmax)
__device__ float g_AS[Bc * (Nc + 1)];        // exclusive prefix sum of Ae  (AS[k] = sum_{j<k})
__device__ float g_ES[Bc * (Nc + 1)];        // suffix sum of Ee            (ES[k] = sum_{j>=k})
__device__ float g_FWD[Bc * Nc * Cc];        // per-chunk inclusive fwd scan of Ae*h
__device__ float g_BWD[Bc * Nc * Cc];        // per-chunk inclusive bwd scan of Ee*h
__device__ float g_TF[Bc * NCHUNK * Cc];     // chunk offsets (exclusive, fwd)
__device__ float g_TB[Bc * NCHUNK * Cc];     // chunk offsets (exclusive, bwd)

// ---------------- Kernel 1: h = text @ W  (M=16384, K=128, N=128) --------
// BM=128, BN=128, BK=16, 256 threads, 8x8 micro-tile per thread.
__global__ __launch_bounds__(256, 1)
void gemm_kernel(const float* __restrict__ X, const float* __restrict__ W) {
    __shared__ float As[16][128];   // [k][m]  (transposed text tile)
    __shared__ float Bs[16][128];   // [k][n]
    const int tid = threadIdx.x;
    const int tx = tid & 15;        // 0..15 -> 8 cols
    const int ty = tid >> 4;        // 0..15 -> 8 rows
    const int m0 = blockIdx.x * 128;

    float acc[8][8];
#pragma unroll
    for (int i = 0; i < 8; i++)
#pragma unroll
        for (int j = 0; j < 8; j++) acc[i][j] = 0.f;

    for (int k0 = 0; k0 < 128; k0 += 16) {
        // load text tile 128x16, store transposed
#pragma unroll
        for (int l = 0; l < 2; l++) {
            int fid = tid + l * 256;          // 0..511 float4s
            int m = fid >> 2;                 // row 0..127
            int kq = (fid & 3) * 4;           // 0,4,8,12
            float4 t = *(const float4*)&X[(m0 + m) * 128 + k0 + kq];
            As[kq + 0][m] = t.x; As[kq + 1][m] = t.y;
            As[kq + 2][m] = t.z; As[kq + 3][m] = t.w;
        }
        // load W tile 16x128
#pragma unroll
        for (int l = 0; l < 2; l++) {
            int fid = tid + l * 256;
            int kk = fid >> 5;                // 0..15
            int nq = (fid & 31) * 4;
            *(float4*)&Bs[kk][nq] = *(const float4*)&W[(k0 + kk) * 128 + nq];
        }
        __syncthreads();
#pragma unroll
        for (int k = 0; k < 16; k++) {
            float a[8], b[8];
            *(float4*)&a[0] = *(float4*)&As[k][ty * 8];
            *(float4*)&a[4] = *(float4*)&As[k][ty * 8 + 4];
            *(float4*)&b[0] = *(float4*)&Bs[k][tx * 8];
            *(float4*)&b[4] = *(float4*)&Bs[k][tx * 8 + 4];
#pragma unroll
            for (int i = 0; i < 8; i++)
#pragma unroll
                for (int j = 0; j < 8; j++) acc[i][j] += a[i] * b[j];
        }
        __syncthreads();
    }
#pragma unroll
    for (int i = 0; i < 8; i++) {
        int m = m0 + ty * 8 + i;
#pragma unroll
        for (int j = 0; j < 8; j += 4) {
            *(float4*)&g_h[m * 128 + tx * 8 + j] =
                make_float4(acc[i][j], acc[i][j + 1], acc[i][j + 2], acc[i][j + 3]);
        }
    }
}

// ---------------- Kernel 2: s1 = h.a1, s2 = h.a2 (one warp per row) ------
__global__ __launch_bounds__(256)
void s12_kernel(const float* __restrict__ a) {
    int row = blockIdx.x * 8 + (threadIdx.x >> 5);
    int lane = threadIdx.x & 31;
    const float* hr = &g_h[row * 128];
    float p1 = 0.f, p2 = 0.f;
#pragma unroll
    for (int j = lane; j < 128; j += 32) {
        float hv = hr[j];
        p1 += hv * a[j];
        p2 += hv * a[128 + j];
    }
#pragma unroll
    for (int o = 16; o; o >>= 1) {
        p1 += __shfl_down_sync(0xffffffffu, p1, o);
        p2 += __shfl_down_sync(0xffffffffu, p2, o);
    }
    if (lane == 0) { g_s1[row] = p1; g_s2[row] = p2; }
}

// ---------------- scan helper: inclusive scan of x[2048] in shared -------
__device__ __forceinline__ void scan2048(float* x, float* aux, int t) {
    float a0 = x[2 * t], a1 = x[2 * t + 1];
    float ps = a0 + a1;
    aux[t] = ps;
    __syncthreads();
#pragma unroll
    for (int off = 1; off < 1024; off <<= 1) {
        float add = (t >= off) ? aux[t - off] : 0.f;
        __syncthreads();
        aux[t] += add;
        __syncthreads();
    }
    float excl = aux[t] - ps;
    x[2 * t]     = excl + a0;
    x[2 * t + 1] = excl + ps;
    __syncthreads();
}

// ---------------- Kernel 3: per-batch bitonic sort + scalar scans --------
__global__ __launch_bounds__(1024)
void sort_kernel() {
    __shared__ float sv[2048];
    __shared__ int   si[2048];
    __shared__ float sx[2048];
    __shared__ float aux[1024];
    const int b = blockIdx.x, t = threadIdx.x;

    sv[t]        = g_s2[b * 2048 + t];
    sv[t + 1024] = g_s2[b * 2048 + t + 1024];
    si[t] = t; si[t + 1024] = t + 1024;
    __syncthreads();

    for (int k = 2; k <= 2048; k <<= 1) {
        for (int j = k >> 1; j > 0; j >>= 1) {
#pragma unroll
            for (int l = 0; l < 2; l++) {
                int i = t + l * 1024;
                int ixj = i ^ j;
                if (ixj > i) {
                    bool asc = ((i & k) == 0);
                    float vi = sv[i], vj = sv[ixj];
                    if ((vi > vj) == asc) {
                        sv[i] = vj; sv[ixj] = vi;
                        int ti = si[i]; si[i] = si[ixj]; si[ixj] = ti;
                    }
                }
            }
            __syncthreads();
        }
    }

    const float vmax = sv[2047];
#pragma unroll
    for (int l = 0; l < 2; l++) {
        int i = t + l * 1024;
        g_v[b * 2048 + i] = sv[i];
        g_perm[b * 2048 + i] = si[i];
    }

    // --- forward exclusive scan of A_k = exp(alpha * v_k) ---
#pragma unroll
    for (int l = 0; l < 2; l++) {
        int i = t + l * 1024;
        float av = expf(ALPHA * sv[i]);
        g_Ae[b * 2048 + i] = av;
        sx[i] = av;
    }
    __syncthreads();
    scan2048(sx, aux, t);
#pragma unroll
    for (int l = 0; l < 2; l++) {
        int i = t + l * 1024;
        g_AS[b * 2049 + i + 1] = sx[i];     // exclusive: AS[k] = inc[k-1]
    }
    if (t == 0) g_AS[b * 2049] = 0.f;
    __syncthreads();

    // --- suffix sum of E_k = exp(v_k - vmax): scan reversed ---
#pragma unroll
    for (int l = 0; l < 2; l++) {
        int i = t + l * 1024;
        float ev = expf(sv[i] - vmax);
        g_Ee[b * 2048 + i] = ev;
        sx[2047 - i] = ev;                   // reversed
    }
    __syncthreads();
    scan2048(sx, aux, t);
#pragma unroll
    for (int l = 0; l < 2; l++) {
        int i = t + l * 1024;
        // inclusive scan of reversed array at position (2047-k) == suffix sum from k
        g_ES[b * 2049 + (2047 - i)] = sx[i];
    }
    if (t == 0) g_ES[b * 2049 + 2048] = 0.f;
}

// ---------------- Kernel 4: chunked vector scans -------------------------
// grid = B * NCHUNK blocks, 256 threads: f = tid&127, dir = tid>>7
__global__ __launch_bounds__(256)
void scanA_kernel() {
    const int b = blockIdx.x >> 4;
    const int c = blockIdx.x & 15;
    const int f = threadIdx.x & 127;
    const int dir = threadIdx.x >> 7;
    const int base = c * CHUNK;
    float run = 0.f;
    if (dir == 0) {
#pragma unroll 4
        for (int r = 0; r < CHUNK; r++) {
            int k = base + r;
            int src = g_perm[b * 2048 + k];
            float hv = g_h[(b * 2048 + src) * 128 + f];
            run += g_Ae[b * 2048 + k] * hv;
            g_FWD[(b * 2048 + k) * 128 + f] = run;
        }
        g_TF[(b * NCHUNK + c) * 128 + f] = run;
    } else {
#pragma unroll 4
        for (int r = CHUNK - 1; r >= 0; r--) {
            int k = base + r;
            int src = g_perm[b * 2048 + k];
            float hv = g_h[(b * 2048 + src) * 128 + f];
            run += g_Ee[b * 2048 + k] * hv;
            g_BWD[(b * 2048 + k) * 128 + f] = run;
        }
        g_TB[(b * NCHUNK + c) * 128 + f] = run;
    }
}

// ---------------- Kernel 5: chunk totals -> exclusive offsets ------------
__global__ __launch_bounds__(256)
void scanB_kernel() {
    const int b = blockIdx.x;
    const int f = threadIdx.x & 127;
    const int dir = threadIdx.x >> 7;
    if (dir == 0) {
        float run = 0.f;
        for (int c = 0; c < NCHUNK; c++) {
            float tt = g_TF[(b * NCHUNK + c) * 128 + f];
            g_TF[(b * NCHUNK + c) * 128 + f] = run;
            run += tt;
        }
    } else {
        float run = 0.f;
        for (int c = NCHUNK - 1; c >= 0; c--) {
            float tt = g_TB[(b * NCHUNK + c) * 128 + f];
            g_TB[(b * NCHUNK + c) * 128 + f] = run;
            run += tt;
        }
    }
}

// ---------------- Kernel 6: output (binary search + combine + ELU) -------
// block = 1024 threads = 8 rows x 128 channels
__global__ __launch_bounds__(1024)
void out_kernel(float* __restrict__ out) {
    __shared__ float sh_c1[8], sh_c2[8];
    __shared__ int   sh_k[8];
    const int f = threadIdx.x & 127;
    const int rr = threadIdx.x >> 7;
    const int row = blockIdx.x * 8 + rr;
    const int b = row >> 11;

    if (f == 0) {
        float s1 = g_s1[row];
        const float* v = &g_v[b * 2048];
        float vmax = v[2047];
        float T = -s1;
        int lo = 0, hi = 2048;
        while (lo < hi) {
            int mid = (lo + hi) >> 1;
            if (v[mid] <= T) lo = mid + 1; else hi = mid;
        }
        int k = lo;                       // #{j : s1 + v_j <= 0}
        float z = s1 + vmax;
        float m = z > 0.f ? z : ALPHA * z;          // row max of leaky_relu
        float c1 = expf(z - m);                      // scale for positive branch
        float c2 = expf(ALPHA * s1 - m);             // scale for negative branch
        float den = c1 * g_ES[b * 2049 + k] + c2 * g_AS[b * 2049 + k];
        float inv = 1.f / den;
        sh_k[rr] = k;
        sh_c1[rr] = c1 * inv;
        sh_c2[rr] = c2 * inv;
    }
    __syncthreads();

    const int k = sh_k[rr];
    const float c1 = sh_c1[rr], c2 = sh_c2[rr];
    float suf = 0.f, pre = 0.f;
    if (k < 2048)
        suf = g_BWD[(b * 2048 + k) * 128 + f] +
              g_TB[(b * NCHUNK + (k >> 7)) * 128 + f];
    if (k > 0)
        pre = g_FWD[(b * 2048 + k - 1) * 128 + f] +
              g_TF[(b * NCHUNK + ((k - 1) >> 7)) * 128 + f];
    float hv = g_h[row * 128 + f];
    float x = c1 * suf + c2 * pre + ALPHA * hv;       // h_prime + alpha*h
    out[row * 128 + f] = x > 0.f ? x : (expf(x) - 1.f);   // elu
}

// ---------------- launcher ----------------
extern "C" void kernel_launch(void* const* d_in, const int* in_sizes, int n_in,
                              void* d_out, int out_size) {
    const float* text = nullptr;
    const float* W = nullptr;
    const float* a = nullptr;
    for (int i = 0; i < n_in; i++) {
        if (in_sizes[i] == Bc * Nc * Cc)      text = (const float*)d_in[i];
        else if (in_sizes[i] == Cc * Cc)      W    = (const float*)d_in[i];
        else if (in_sizes[i] == 2 * Cc)       a    = (const float*)d_in[i];
        // adj (Bc*Nc*Nc) is unused by the reference math
    }
    float* out = (float*)d_out;

    gemm_kernel<<<(Bc * Nc) / 128, 256>>>(text, W);
    s12_kernel<<<(Bc * Nc) / 8, 256>>>(a);
    sort_kernel<<<Bc, 1024>>>();
    scanA_kernel<<<Bc * NCHUNK, 256>>>();
    scanB_kernel<<<Bc, 256>>>();
    out_kernel<<<(Bc * Nc) / 8, 1024>>>(out);
}

// round 3
// speedup vs baseline: 2.1648x; 2.1648x over previous
#include <cuda_runtime.h>
#include <math.h>

#define ALPHA 0.2f
constexpr int Bc = 8;
constexpr int Nc = 2048;
constexpr int Cc = 128;
constexpr int NCH = 64;            // chunks per batch
constexpr int CHK = 32;            // rows per chunk

// ---------------- device scratch (no allocations allowed) ----------------
__device__ __align__(16) float g_h[Bc * Nc * Cc];     // h = text @ W
__device__ float g_s1[Bc * Nc];
__device__ float g_s2[Bc * Nc];
__device__ float g_v[Bc * Nc];                        // sorted s2 (ascending) per batch
__device__ int   g_perm[Bc * Nc];                     // sorted k -> original row j
__device__ float g_Ae[Bc * Nc];                       // exp(alpha * v_k)
__device__ float g_Ee[Bc * Nc];                       // exp(v_k - vmax)
__device__ float g_AS[Bc * (Nc + 1)];                 // exclusive prefix sum of Ae
__device__ float g_ES[Bc * (Nc + 1)];                 // suffix sum of Ee
__device__ __align__(16) float g_FWD[Bc * Nc * Cc];   // per-chunk incl fwd scan of Ae*h
__device__ __align__(16) float g_BWD[Bc * Nc * Cc];   // per-chunk incl bwd scan of Ee*h
__device__ __align__(16) float g_TF[Bc * NCH * Cc];   // chunk offsets (exclusive, fwd)
__device__ __align__(16) float g_TB[Bc * NCH * Cc];   // chunk offsets (exclusive, bwd)

// ---------------- Kernel 1: h = text @ W  (M=16384, K=128, N=128) --------
__global__ __launch_bounds__(256, 1)
void gemm_kernel(const float* __restrict__ X, const float* __restrict__ W) {
    __shared__ float As[16][128];   // [k][m]
    __shared__ float Bs[16][128];   // [k][n]
    const int tid = threadIdx.x;
    const int tx = tid & 15;
    const int ty = tid >> 4;
    const int m0 = blockIdx.x * 128;

    float acc[8][8];
#pragma unroll
    for (int i = 0; i < 8; i++)
#pragma unroll
        for (int j = 0; j < 8; j++) acc[i][j] = 0.f;

    for (int k0 = 0; k0 < 128; k0 += 16) {
#pragma unroll
        for (int l = 0; l < 2; l++) {
            int fid = tid + l * 256;
            int m = fid >> 2;
            int kq = (fid & 3) * 4;
            float4 t = *(const float4*)&X[(m0 + m) * 128 + k0 + kq];
            As[kq + 0][m] = t.x; As[kq + 1][m] = t.y;
            As[kq + 2][m] = t.z; As[kq + 3][m] = t.w;
        }
#pragma unroll
        for (int l = 0; l < 2; l++) {
            int fid = tid + l * 256;
            int kk = fid >> 5;
            int nq = (fid & 31) * 4;
            *(float4*)&Bs[kk][nq] = *(const float4*)&W[(k0 + kk) * 128 + nq];
        }
        __syncthreads();
#pragma unroll
        for (int k = 0; k < 16; k++) {
            float a[8], b[8];
            *(float4*)&a[0] = *(float4*)&As[k][ty * 8];
            *(float4*)&a[4] = *(float4*)&As[k][ty * 8 + 4];
            *(float4*)&b[0] = *(float4*)&Bs[k][tx * 8];
            *(float4*)&b[4] = *(float4*)&Bs[k][tx * 8 + 4];
#pragma unroll
            for (int i = 0; i < 8; i++)
#pragma unroll
                for (int j = 0; j < 8; j++) acc[i][j] += a[i] * b[j];
        }
        __syncthreads();
    }
#pragma unroll
    for (int i = 0; i < 8; i++) {
        int m = m0 + ty * 8 + i;
#pragma unroll
        for (int j = 0; j < 8; j += 4) {
            *(float4*)&g_h[m * 128 + tx * 8 + j] =
                make_float4(acc[i][j], acc[i][j + 1], acc[i][j + 2], acc[i][j + 3]);
        }
    }
}

// ---------------- Kernel 2: s1 = h.a1, s2 = h.a2 (one warp per row) ------
__global__ __launch_bounds__(256)
void s12_kernel(const float* __restrict__ a) {
    int row = blockIdx.x * 8 + (threadIdx.x >> 5);
    int lane = threadIdx.x & 31;
    const float4* hr = (const float4*)&g_h[row * 128];
    float4 hv = hr[lane];
    float4 a1 = ((const float4*)a)[lane];
    float4 a2 = ((const float4*)a)[32 + lane];
    float p1 = hv.x * a1.x + hv.y * a1.y + hv.z * a1.z + hv.w * a1.w;
    float p2 = hv.x * a2.x + hv.y * a2.y + hv.z * a2.z + hv.w * a2.w;
#pragma unroll
    for (int o = 16; o; o >>= 1) {
        p1 += __shfl_down_sync(0xffffffffu, p1, o);
        p2 += __shfl_down_sync(0xffffffffu, p2, o);
    }
    if (lane == 0) { g_s1[row] = p1; g_s2[row] = p2; }
}

// ---------------- scan helper: inclusive scan of x[2048] in shared -------
__device__ __forceinline__ void scan2048(float* x, float* aux, int t) {
    float a0 = x[2 * t], a1 = x[2 * t + 1];
    float ps = a0 + a1;
    aux[t] = ps;
    __syncthreads();
#pragma unroll
    for (int off = 1; off < 1024; off <<= 1) {
        float add = (t >= off) ? aux[t - off] : 0.f;
        __syncthreads();
        aux[t] += add;
        __syncthreads();
    }
    float excl = aux[t] - ps;
    x[2 * t]     = excl + a0;
    x[2 * t + 1] = excl + ps;
    __syncthreads();
}

// float -> order-preserving uint32
__device__ __forceinline__ unsigned f2o(float x) {
    unsigned u = __float_as_uint(x);
    return u ^ ((u >> 31) ? 0xFFFFFFFFu : 0x80000000u);
}
__device__ __forceinline__ float o2f(unsigned u) {
    u ^= (u & 0x80000000u) ? 0x80000000u : 0xFFFFFFFFu;
    return __uint_as_float(u);
}

// ---------------- Kernel 3: per-batch bitonic sort (u64 keys) + scans ----
__global__ __launch_bounds__(1024)
void sort_kernel() {
    __shared__ unsigned long long sk[2048];   // (orderable(s2) << 32) | idx
    __shared__ float sx[2048];
    __shared__ float aux[1024];
    const int b = blockIdx.x, t = threadIdx.x;

#pragma unroll
    for (int l = 0; l < 2; l++) {
        int i = t + l * 1024;
        sk[i] = ((unsigned long long)f2o(g_s2[b * 2048 + i]) << 32) | (unsigned)i;
    }
    __syncthreads();

    for (int k = 2; k <= 2048; k <<= 1) {
        for (int j = k >> 1; j > 0; j >>= 1) {
#pragma unroll
            for (int l = 0; l < 2; l++) {
                int i = t + l * 1024;
                int ixj = i ^ j;
                if (ixj > i) {
                    bool asc = ((i & k) == 0);
                    unsigned long long vi = sk[i], vj = sk[ixj];
                    if ((vi > vj) == asc) { sk[i] = vj; sk[ixj] = vi; }
                }
            }
            __syncthreads();
        }
    }

    float sv0 = o2f((unsigned)(sk[t] >> 32));
    float sv1 = o2f((unsigned)(sk[t + 1024] >> 32));
    const float vmax = o2f((unsigned)(sk[2047] >> 32));

    g_v[b * 2048 + t]        = sv0;
    g_v[b * 2048 + t + 1024] = sv1;
    g_perm[b * 2048 + t]        = (int)(unsigned)sk[t];
    g_perm[b * 2048 + t + 1024] = (int)(unsigned)sk[t + 1024];

    // --- forward exclusive scan of A_k = exp(alpha * v_k) ---
    float av0 = expf(ALPHA * sv0), av1 = expf(ALPHA * sv1);
    g_Ae[b * 2048 + t] = av0;  g_Ae[b * 2048 + t + 1024] = av1;
    sx[t] = av0; sx[t + 1024] = av1;
    __syncthreads();
    scan2048(sx, aux, t);
    g_AS[b * 2049 + t + 1]        = sx[t];
    g_AS[b * 2049 + t + 1024 + 1] = sx[t + 1024];
    if (t == 0) g_AS[b * 2049] = 0.f;
    __syncthreads();

    // --- suffix sum of E_k = exp(v_k - vmax) via reversed scan ---
    float ev0 = expf(sv0 - vmax), ev1 = expf(sv1 - vmax);
    g_Ee[b * 2048 + t] = ev0;  g_Ee[b * 2048 + t + 1024] = ev1;
    sx[2047 - t] = ev0;  sx[2047 - (t + 1024)] = ev1;
    __syncthreads();
    scan2048(sx, aux, t);
    g_ES[b * 2049 + (2047 - t)]          = sx[t];
    g_ES[b * 2049 + (2047 - (t + 1024))] = sx[t + 1024];
    if (t == 0) g_ES[b * 2049 + 2048] = 0.f;
}

// ---------------- Kernel 4: chunked vector scans (float4) ----------------
// grid = B * NCH, block = 64: dir = tid>>5, lane = tid&31 (float4 channel)
__global__ __launch_bounds__(64)
void scanA_kernel() {
    const int b = blockIdx.x >> 6;
    const int c = blockIdx.x & 63;
    const int dir = threadIdx.x >> 5;
    const int lane = threadIdx.x & 31;
    const int kb = b * 2048 + c * CHK;
    const float4* h4 = (const float4*)g_h;
    float4 run = make_float4(0.f, 0.f, 0.f, 0.f);
    if (dir == 0) {
        float4* o4 = (float4*)g_FWD;
#pragma unroll 8
        for (int r = 0; r < CHK; r++) {
            int k = kb + r;
            int src = __ldg(&g_perm[k]);
            float w = __ldg(&g_Ae[k]);
            float4 hv = h4[((b * 2048 + src) << 5) + lane];
            run.x += w * hv.x; run.y += w * hv.y;
            run.z += w * hv.z; run.w += w * hv.w;
            o4[(k << 5) + lane] = run;
        }
        ((float4*)g_TF)[((b * NCH + c) << 5) + lane] = run;
    } else {
        float4* o4 = (float4*)g_BWD;
#pragma unroll 8
        for (int r = CHK - 1; r >= 0; r--) {
            int k = kb + r;
            int src = __ldg(&g_perm[k]);
            float w = __ldg(&g_Ee[k]);
            float4 hv = h4[((b * 2048 + src) << 5) + lane];
            run.x += w * hv.x; run.y += w * hv.y;
            run.z += w * hv.z; run.w += w * hv.w;
            o4[(k << 5) + lane] = run;
        }
        ((float4*)g_TB)[((b * NCH + c) << 5) + lane] = run;
    }
}

// ---------------- Kernel 5: chunk totals -> exclusive offsets ------------
// grid = B*2 (dir), block = 32 (float4 lanes)
__global__ __launch_bounds__(32)
void scanB_kernel() {
    const int b = blockIdx.x >> 1;
    const int dir = blockIdx.x & 1;
    const int lane = threadIdx.x;
    if (dir == 0) {
        float4* T4 = (float4*)g_TF;
        float4 run = make_float4(0.f, 0.f, 0.f, 0.f);
#pragma unroll 8
        for (int c = 0; c < NCH; c++) {
            float4 tt = T4[((b * NCH + c) << 5) + lane];
            T4[((b * NCH + c) << 5) + lane] = run;
            run.x += tt.x; run.y += tt.y; run.z += tt.z; run.w += tt.w;
        }
    } else {
        float4* T4 = (float4*)g_TB;
        float4 run = make_float4(0.f, 0.f, 0.f, 0.f);
#pragma unroll 8
        for (int c = NCH - 1; c >= 0; c--) {
            float4 tt = T4[((b * NCH + c) << 5) + lane];
            T4[((b * NCH + c) << 5) + lane] = run;
            run.x += tt.x; run.y += tt.y; run.z += tt.z; run.w += tt.w;
        }
    }
}

// ---------------- Kernel 6: output (binary search + combine + ELU) -------
// block = 256 = 8 rows x 32 lanes (float4)
__global__ __launch_bounds__(256)
void out_kernel(float* __restrict__ out) {
    __shared__ float sh_c1[8], sh_c2[8];
    __shared__ int   sh_k[8];
    const int lane = threadIdx.x & 31;
    const int rr = threadIdx.x >> 5;
    const int row = blockIdx.x * 8 + rr;
    const int b = row >> 11;

    if (lane == 0) {
        float s1 = g_s1[row];
        const float* v = &g_v[b * 2048];
        float vmax = v[2047];
        float T = -s1;
        int lo = 0, hi = 2048;
        while (lo < hi) {
            int mid = (lo + hi) >> 1;
            if (v[mid] <= T) lo = mid + 1; else hi = mid;
        }
        int k = lo;
        float z = s1 + vmax;
        float m = z > 0.f ? z : ALPHA * z;
        float c1 = expf(z - m);
        float c2 = expf(ALPHA * s1 - m);
        float den = c1 * g_ES[b * 2049 + k] + c2 * g_AS[b * 2049 + k];
        float inv = 1.f / den;
        sh_k[rr] = k;
        sh_c1[rr] = c1 * inv;
        sh_c2[rr] = c2 * inv;
    }
    __syncthreads();

    const int k = sh_k[rr];
    const float c1 = sh_c1[rr], c2 = sh_c2[rr];
    float4 suf = make_float4(0.f, 0.f, 0.f, 0.f);
    float4 pre = make_float4(0.f, 0.f, 0.f, 0.f);
    if (k < 2048) {
        float4 s0 = ((const float4*)g_BWD)[((b * 2048 + k) << 5) + lane];
        float4 t0 = ((const float4*)g_TB)[((b * NCH + (k >> 5)) << 5) + lane];
        suf.x = s0.x + t0.x; suf.y = s0.y + t0.y;
        suf.z = s0.z + t0.z; suf.w = s0.w + t0.w;
    }
    if (k > 0) {
        float4 s0 = ((const float4*)g_FWD)[((b * 2048 + k - 1) << 5) + lane];
        float4 t0 = ((const float4*)g_TF)[((b * NCH + ((k - 1) >> 5)) << 5) + lane];
        pre.x = s0.x + t0.x; pre.y = s0.y + t0.y;
        pre.z = s0.z + t0.z; pre.w = s0.w + t0.w;
    }
    float4 hv = ((const float4*)g_h)[(row << 5) + lane];
    float4 o;
    o.x = c1 * suf.x + c2 * pre.x + ALPHA * hv.x;
    o.y = c1 * suf.y + c2 * pre.y + ALPHA * hv.y;
    o.z = c1 * suf.z + c2 * pre.z + ALPHA * hv.z;
    o.w = c1 * suf.w + c2 * pre.w + ALPHA * hv.w;
    o.x = o.x > 0.f ? o.x : (expf(o.x) - 1.f);
    o.y = o.y > 0.f ? o.y : (expf(o.y) - 1.f);
    o.z = o.z > 0.f ? o.z : (expf(o.z) - 1.f);
    o.w = o.w > 0.f ? o.w : (expf(o.w) - 1.f);
    ((float4*)out)[(row << 5) + lane] = o;
}

// ---------------- launcher ----------------
extern "C" void kernel_launch(void* const* d_in, const int* in_sizes, int n_in,
                              void* d_out, int out_size) {
    const float* text = nullptr;
    const float* W = nullptr;
    const float* a = nullptr;
    for (int i = 0; i < n_in; i++) {
        if (in_sizes[i] == Bc * Nc * Cc)      text = (const float*)d_in[i];
        else if (in_sizes[i] == Cc * Cc)      W    = (const float*)d_in[i];
        else if (in_sizes[i] == 2 * Cc)       a    = (const float*)d_in[i];
        // adj (Bc*Nc*Nc) is mathematically unused by the reference
    }
    float* out = (float*)d_out;

    gemm_kernel<<<(Bc * Nc) / 128, 256>>>(text, W);
    s12_kernel<<<(Bc * Nc) / 8, 256>>>(a);
    sort_kernel<<<Bc, 1024>>>();
    scanA_kernel<<<Bc * NCH, 64>>>();
    scanB_kernel<<<Bc * 2, 32>>>();
    out_kernel<<<(Bc * Nc) / 8, 256>>>(out);
}